// round 12
// baseline (speedup 1.0000x reference)
#include <cuda_runtime.h>

#define BB 2
#define HH 160
#define WW 160
#define NPTS 2048
#define HW (HH*WW)
#define TOTAL (BB*HW)        // 51200
#define NV4 (TOTAL/4)        // 12800 float4s
#define NTHR 512
#define NBLK 26              // 26*512 = 13312 float4 slots >= 12800
#define PIX_PER_BLK (NTHR*4) // 2048 pixels per block slice
#define PPT 8                // 4096 points / 512 threads
#define LMASKW (PIX_PER_BLK/32)  // 64 words
#define DOWN 16.0f
#define HALF 7.5f
#define INV  (1.0f/16.0f)
#define FSCALE 1048576.0f    // 2^20 fixed-point scale
#define BIAS   (1LL << 40)   // keeps each block's addend positive
#define CNT_SHIFT 52
#define VAL_MASK ((1ULL << 52) - 1)

// Single packed accumulator: {count:12 | biased sum:52}. Zero-init; the last
// block resets it with atomicExch, so every graph replay starts clean.
__device__ unsigned long long g_pack;

__device__ __forceinline__ float warp_sum(float v) {
    #pragma unroll
    for (int o = 16; o > 0; o >>= 1) v += __shfl_down_sync(0xffffffffu, v, o);
    return v;
}

// softplus(a) = max(a,0) + log1p(exp(-|a|)); fast fp32 MUFU version
__device__ __forceinline__ float softplus(float a) {
    return fmaxf(a, 0.0f) + __logf(1.0f + __expf(-fabsf(a)));
}

__global__ __launch_bounds__(NTHR, 1)
void p2r_fused(const float* __restrict__ dens, const float* __restrict__ pts,
               float* __restrict__ out) {
    __shared__ float    s_red[NTHR / 32];    // 16 per-warp partials
    __shared__ unsigned s_mask[LMASKW];      // bit per pixel of THIS slice

    const int tid  = threadIdx.x;
    const int lane = tid & 31;
    const int w    = tid >> 5;
    const int bid  = blockIdx.x;

    // ---- issue dense load (1 float4 = 4 pixels) immediately ----
    const int fi = bid * NTHR + tid;
    const bool valid = fi < NV4;
    float4 a = valid ? ((const float4*)dens)[fi] : make_float4(0.f, 0.f, 0.f, 0.f);

    // ---- issue point loads: 8 points = 4 float4 (L2-hot, front-batched) ----
    const float4* p4 = (const float4*)pts;
    float4 pp[PPT / 2];
    #pragma unroll
    for (int q = 0; q < PPT / 2; q++) pp[q] = p4[tid * (PPT / 2) + q];

    // zero mask while loads are in flight; BARRIER before any atomicOr
    if (tid < LMASKW) s_mask[tid] = 0u;
    __syncthreads();

    // ---- rasterize: mark points whose nearest pixel falls in MY slice ----
    // nearest index = rint((p-7.5)/16), UNCLAMPED: p in [0,2560) gives idx in
    // [0,160]; idx==160 implies axis distance >= 8 -> fails d2<64, so the
    // masked atomicOr never fires for out-of-range indices. No clamps needed.
    const int b    = tid >> 8;             // points 8t..8t+7 share batch
    const int base = bid * PIX_PER_BLK;    // my slice: [base, base+2048)
    #pragma unroll
    for (int q = 0; q < PPT / 2; q++) {
        #pragma unroll
        for (int h = 0; h < 2; h++) {
            const float p0 = h ? pp[q].z : pp[q].x;   // y
            const float p1 = h ? pp[q].w : pp[q].y;   // x
            const float fy = rintf(fmaf(p0, INV, -(HALF * INV)));
            const float fx = rintf(fmaf(p1, INV, -(HALF * INV)));
            const float dy = fmaf(fy, DOWN, HALF - p0);
            const float dx = fmaf(fx, DOWN, HALF - p1);
            // sqrtf(d2) < 8  <=>  d2 < 64 (sqrt monotone, correctly rounded)
            const int off = b * HW + (int)fy * WW + (int)fx - base;
            if ((dy * dy + dx * dx) < 64.0f && (unsigned)off < PIX_PER_BLK)
                atomicOr(&s_mask[off >> 5], 1u << (off & 31));  // same-value races OK
        }
    }
    __syncthreads();

    // ---- fold: softplus(A) + [marked]*(softplus(A) - 2A) over my 4 pixels ----
    float v = 0.0f;
    if (valid) {
        const unsigned m = s_mask[tid >> 3] >> ((tid & 7) * 4);  // my 4 bits
        float sp;
        sp = softplus(a.x); v += sp + ((m & 1u) ? sp - 2.0f * a.x : 0.0f);
        sp = softplus(a.y); v += sp + ((m & 2u) ? sp - 2.0f * a.y : 0.0f);
        sp = softplus(a.z); v += sp + ((m & 4u) ? sp - 2.0f * a.z : 0.0f);
        sp = softplus(a.w); v += sp + ((m & 8u) ? sp - 2.0f * a.w : 0.0f);
    }

    // ---- block reduce: per-warp shfl tree -> s_red -> warp0 tree ----
    v = warp_sum(v);
    if (lane == 0) s_red[w] = v;
    __syncthreads();
    if (w != 0) return;
    v = (lane < NTHR / 32) ? s_red[lane] : 0.0f;
    #pragma unroll
    for (int o = 8; o > 0; o >>= 1) v += __shfl_down_sync(0xffffu, v, o);

    // ---- ONE global atomic: {count|sum} packed; winner holds the full sum ----
    if (lane == 0) {
        const long long iv = (long long)__float2ll_rn(v * FSCALE);
        const unsigned long long ticket =
            (1ULL << CNT_SHIFT) + (unsigned long long)(iv + BIAS);
        const unsigned long long old = atomicAdd(&g_pack, ticket);
        if ((unsigned)(old >> CNT_SHIFT) == NBLK - 1) {   // I'm the last arrival
            const unsigned long long full = old + ticket; // complete packed sum
            const long long s =
                (long long)(full & VAL_MASK) - (long long)NBLK * BIAS;
            out[0] = (float)s * (1.0f / FSCALE) * (1.0f / (float)TOTAL);
            atomicExch(&g_pack, 0ULL);                    // reset for next replay
        }
    }
}

extern "C" void kernel_launch(void* const* d_in, const int* in_sizes, int n_in,
                              void* d_out, int out_size) {
    const float* dens = (const float*)d_in[0];
    const float* pts  = (const float*)d_in[1];
    p2r_fused<<<NBLK, NTHR>>>(dens, pts, (float*)d_out);
}

// round 13
// speedup vs baseline: 1.2415x; 1.2415x over previous
#include <cuda_runtime.h>

#define BB 2
#define HH 160
#define WW 160
#define NPTS 2048
#define HW (HH*WW)
#define TOTAL (BB*HW)        // 51200
#define NV4 (TOTAL/4)        // 12800 float4s
#define NTHR 1024
#define NBLK 13              // 13*1024 = 13312 float4 slots >= 12800
#define PIX_PER_BLK (NTHR*4) // 4096 pixels per block slice
#define LMASKW (PIX_PER_BLK/32)  // 128 words
#define DOWN 16.0f
#define HALF 7.5f
#define INV  (1.0f/16.0f)
#define FSCALE 1048576.0f    // 2^20 fixed-point scale
#define BIAS   (1LL << 40)   // keeps each block's addend positive
#define CNT_SHIFT 52
#define VAL_MASK ((1ULL << 52) - 1)

// Single packed accumulator: {count:12 | biased sum:52}. Zero-init; the last
// block resets it with atomicExch, so every graph replay starts clean.
__device__ unsigned long long g_pack;

__device__ __forceinline__ float warp_sum(float v) {
    #pragma unroll
    for (int o = 16; o > 0; o >>= 1) v += __shfl_down_sync(0xffffffffu, v, o);
    return v;
}

// softplus(a) = max(a,0) + log1p(exp(-|a|)); fast fp32 MUFU version
__device__ __forceinline__ float softplus(float a) {
    return fmaxf(a, 0.0f) + __logf(1.0f + __expf(-fabsf(a)));
}

__global__ __launch_bounds__(NTHR, 1)
void p2r_fused(const float* __restrict__ dens, const float* __restrict__ pts,
               float* __restrict__ out) {
    __shared__ float    s_red[NTHR / 32];    // 32 per-warp partials, no conflicts
    __shared__ unsigned s_mask[LMASKW];      // bit per pixel of THIS slice

    const int tid  = threadIdx.x;
    const int lane = tid & 31;
    const int w    = tid >> 5;
    const int bid  = blockIdx.x;

    // ---- issue dense load (1 float4 = 4 pixels) immediately ----
    const int fi = bid * NTHR + tid;
    const bool valid = fi < NV4;
    float4 a = valid ? ((const float4*)dens)[fi] : make_float4(0.f, 0.f, 0.f, 0.f);

    // ---- issue point loads (4 points = 2 float4, L2-hot) ----
    const float4* p4 = (const float4*)pts;
    float4 pp0 = p4[2 * tid];
    float4 pp1 = p4[2 * tid + 1];

    // zero mask while loads are in flight; BARRIER before any atomicOr
    if (tid < LMASKW) s_mask[tid] = 0u;
    __syncthreads();

    // ---- rasterize: mark points whose nearest pixel falls in MY slice ----
    // nearest index = rint((p-7.5)/16), UNCLAMPED: p in [0,2560) gives idx in
    // [0,160]; idx==160 implies axis distance >= 8 -> fails d2<64, so the
    // masked atomicOr never fires for out-of-range indices. No clamps needed.
    const int b    = tid >> 9;             // points 4t..4t+3 share batch
    const int base = bid * PIX_PER_BLK;    // my slice: [base, base+4096)
    #pragma unroll
    for (int q = 0; q < 2; q++) {
        const float4 pq = q ? pp1 : pp0;
        #pragma unroll
        for (int h = 0; h < 2; h++) {
            const float p0 = h ? pq.z : pq.x;   // y
            const float p1 = h ? pq.w : pq.y;   // x
            const float fy = rintf(fmaf(p0, INV, -(HALF * INV)));
            const float fx = rintf(fmaf(p1, INV, -(HALF * INV)));
            const float dy = fmaf(fy, DOWN, HALF - p0);
            const float dx = fmaf(fx, DOWN, HALF - p1);
            // sqrtf(d2) < 8  <=>  d2 < 64 (sqrt monotone, correctly rounded)
            const int off = b * HW + (int)fy * WW + (int)fx - base;
            if ((dy * dy + dx * dx) < 64.0f && (unsigned)off < PIX_PER_BLK)
                atomicOr(&s_mask[off >> 5], 1u << (off & 31));  // same-value races OK
        }
    }
    __syncthreads();

    // ---- fold: softplus(A) + [marked]*(softplus(A) - 2A) over my 4 pixels ----
    float v = 0.0f;
    if (valid) {
        const unsigned m = s_mask[tid >> 3] >> ((tid & 7) * 4);  // my 4 bits
        float sp;
        sp = softplus(a.x); v += sp + ((m & 1u) ? sp - 2.0f * a.x : 0.0f);
        sp = softplus(a.y); v += sp + ((m & 2u) ? sp - 2.0f * a.y : 0.0f);
        sp = softplus(a.z); v += sp + ((m & 4u) ? sp - 2.0f * a.z : 0.0f);
        sp = softplus(a.w); v += sp + ((m & 8u) ? sp - 2.0f * a.w : 0.0f);
    }

    // ---- block reduce: per-warp shfl tree -> s_red -> warp0 shfl tree ----
    v = warp_sum(v);
    if (lane == 0) s_red[w] = v;
    __syncthreads();
    if (w != 0) return;
    v = warp_sum(s_red[lane]);           // NTHR/32 == 32: all lanes valid

    // ---- ONE global atomic: {count|sum} packed; winner holds the full sum ----
    if (lane == 0) {
        const long long iv = (long long)__float2ll_rn(v * FSCALE);
        const unsigned long long ticket =
            (1ULL << CNT_SHIFT) + (unsigned long long)(iv + BIAS);
        const unsigned long long old = atomicAdd(&g_pack, ticket);
        if ((unsigned)(old >> CNT_SHIFT) == NBLK - 1) {   // I'm the last arrival
            const unsigned long long full = old + ticket; // complete packed sum
            const long long s =
                (long long)(full & VAL_MASK) - (long long)NBLK * BIAS;
            out[0] = (float)s * (1.0f / FSCALE) * (1.0f / (float)TOTAL);
            atomicExch(&g_pack, 0ULL);                    // reset for next replay
        }
    }
}

extern "C" void kernel_launch(void* const* d_in, const int* in_sizes, int n_in,
                              void* d_out, int out_size) {
    const float* dens = (const float*)d_in[0];
    const float* pts  = (const float*)d_in[1];
    p2r_fused<<<NBLK, NTHR>>>(dens, pts, (float*)d_out);
}